// round 15
// baseline (speedup 1.0000x reference)
#include <cuda_runtime.h>
#include <cuda_bf16.h>
#include <cuda_fp16.h>
#include <math.h>
#include <stdint.h>

#define B_ 2
#define S_ 2048
#define D_ 2048
#define H_ 16
#define HD_ 128

// ---------------- device scratch (no runtime allocation) ----------------
__device__ __nv_bfloat16 g_xhi[B_ * S_ * D_];
__device__ __nv_bfloat16 g_xlo[B_ * S_ * D_];
__device__ __half g_x16[B_ * S_ * D_];
__device__ __nv_bfloat16 g_wqhi[D_ * D_], g_wqlo[D_ * D_];
__device__ __nv_bfloat16 g_wkhi[D_ * D_], g_wklo[D_ * D_];
__device__ __half g_wv16[D_ * D_];
__device__ __half g_wo16[D_ * D_];
__device__ __half g_ao16[B_ * S_ * D_];

// attention operands (head layout [b][h][s][hd])
__device__ __nv_bfloat16 g_qh[B_ * H_ * S_ * HD_], g_ql[B_ * H_ * S_ * HD_];
__device__ __nv_bfloat16 g_kh[B_ * H_ * S_ * HD_], g_kl[B_ * H_ * S_ * HD_];
__device__ __half g_v16[B_ * H_ * S_ * HD_];

__device__ float g_cos[S_ * 64];
__device__ float g_sin[S_ * 64];

// ---------------- helpers ----------------
__device__ __forceinline__ uint32_t smem_u32(const void* p) {
    uint32_t a;
    asm("{ .reg .u64 t; cvta.to.shared.u64 t, %1; cvt.u32.u64 %0, t; }"
        : "=r"(a) : "l"(p));
    return a;
}
static __device__ __forceinline__ uint32_t swz128(uint32_t o) {
    return o ^ ((o >> 3) & 0x70);
}
static __device__ __forceinline__ uint32_t swz64(uint32_t o) {
    return o ^ ((o >> 3) & 0x30);
}
static __device__ __forceinline__ uint32_t swzf(uint32_t row, uint32_t colbyte) {
    return row * 256u + (colbyte ^ ((row & 7u) << 4));
}
__device__ __forceinline__ void cp16(uint32_t saddr, const void* gptr) {
    asm volatile("cp.async.cg.shared.global [%0], [%1], 16;"
                 :: "r"(saddr), "l"(gptr) : "memory");
}
#define CP_COMMIT() asm volatile("cp.async.commit_group;" ::: "memory")

__device__ __forceinline__ void ldsm_x4(uint32_t a, uint32_t* r) {
    asm volatile("ldmatrix.sync.aligned.m8n8.x4.shared.b16 {%0,%1,%2,%3}, [%4];"
                 : "=r"(r[0]), "=r"(r[1]), "=r"(r[2]), "=r"(r[3]) : "r"(a));
}
__device__ __forceinline__ void ldsm_x4t(uint32_t a, uint32_t* r) {
    asm volatile("ldmatrix.sync.aligned.m8n8.x4.trans.shared.b16 {%0,%1,%2,%3}, [%4];"
                 : "=r"(r[0]), "=r"(r[1]), "=r"(r[2]), "=r"(r[3]) : "r"(a));
}
__device__ __forceinline__ void mma16816(float* d, const uint32_t* a, const uint32_t* b) {
    asm volatile(
        "mma.sync.aligned.m16n8k16.row.col.f32.bf16.bf16.f32 "
        "{%0,%1,%2,%3}, {%4,%5,%6,%7}, {%8,%9}, {%0,%1,%2,%3};"
        : "+f"(d[0]), "+f"(d[1]), "+f"(d[2]), "+f"(d[3])
        : "r"(a[0]), "r"(a[1]), "r"(a[2]), "r"(a[3]), "r"(b[0]), "r"(b[1]));
}
__device__ __forceinline__ void mma16816h(float* d, const uint32_t* a, const uint32_t* b) {
    asm volatile(
        "mma.sync.aligned.m16n8k16.row.col.f32.f16.f16.f32 "
        "{%0,%1,%2,%3}, {%4,%5,%6,%7}, {%8,%9}, {%0,%1,%2,%3};"
        : "+f"(d[0]), "+f"(d[1]), "+f"(d[2]), "+f"(d[3])
        : "r"(a[0]), "r"(a[1]), "r"(a[2]), "r"(a[3]), "r"(b[0]), "r"(b[1]));
}
__device__ __forceinline__ uint32_t packh2(float x, float y) {
    half2 t = __floats2half2_rn(x, y);
    return *(uint32_t*)&t;
}
__device__ __forceinline__ void split1(float x, __nv_bfloat16& h, __nv_bfloat16& l) {
    h = __float2bfloat16(x);
    l = __float2bfloat16(x - __bfloat162float(h));
}

// ---------------------------------------------------------------------------
// Mega prep kernel (unchanged).
// ---------------------------------------------------------------------------
#define PREP_BLOCKS 25088

__global__ void prep_all(const float* __restrict__ x,
                         const float* __restrict__ Wq, const float* __restrict__ Wk,
                         const float* __restrict__ Wv, const float* __restrict__ Wo)
{
    const int bid = blockIdx.x;
    const int t   = threadIdx.x;

    if (bid < 512) {
        const int idx = bid * 256 + t;
        const int i = idx & 63;
        const int s = idx >> 6;
        const float inv_freq = (float)pow(10000.0, -(double)i * (1.0 / 64.0));
        const double ang = (double)s * (double)inv_freq;
        double sd, cd;
        sincos(ang, &sd, &cd);
        g_cos[idx] = (float)cd;
        g_sin[idx] = (float)sd;
        return;
    }
    if (bid < 8704) {
        const int i = (bid - 512) * 256 + t;
        float4 v = ((const float4*)x)[i];
        __nv_bfloat16 h0, h1, h2, h3, l0, l1, l2, l3;
        split1(v.x, h0, l0); split1(v.y, h1, l1);
        split1(v.z, h2, l2); split1(v.w, h3, l3);
        ((__nv_bfloat162*)g_xhi)[2 * i]     = __nv_bfloat162(h0, h1);
        ((__nv_bfloat162*)g_xhi)[2 * i + 1] = __nv_bfloat162(h2, h3);
        ((__nv_bfloat162*)g_xlo)[2 * i]     = __nv_bfloat162(l0, l1);
        ((__nv_bfloat162*)g_xlo)[2 * i + 1] = __nv_bfloat162(l2, l3);
        ((half2*)g_x16)[2 * i]     = __floats2half2_rn(v.x, v.y);
        ((half2*)g_x16)[2 * i + 1] = __floats2half2_rn(v.z, v.w);
        return;
    }
    if (bid < 16896) {
        const bool is_q = bid < 12800;
        const int i = (bid - (is_q ? 8704 : 12800)) * 256 + t;
        const float* w = is_q ? Wq : Wk;
        __nv_bfloat16* hi = is_q ? g_wqhi : g_wkhi;
        __nv_bfloat16* lo = is_q ? g_wqlo : g_wklo;
        float4 v = ((const float4*)w)[i];
        __nv_bfloat16 h0, h1, h2, h3, l0, l1, l2, l3;
        split1(v.x, h0, l0); split1(v.y, h1, l1);
        split1(v.z, h2, l2); split1(v.w, h3, l3);
        ((__nv_bfloat162*)hi)[2 * i]     = __nv_bfloat162(h0, h1);
        ((__nv_bfloat162*)hi)[2 * i + 1] = __nv_bfloat162(h2, h3);
        ((__nv_bfloat162*)lo)[2 * i]     = __nv_bfloat162(l0, l1);
        ((__nv_bfloat162*)lo)[2 * i + 1] = __nv_bfloat162(l2, l3);
        return;
    }
    {
        const bool is_v = bid < 20992;
        const int i = (bid - (is_v ? 16896 : 20992)) * 256 + t;
        const float* w = is_v ? Wv : Wo;
        __half* o = is_v ? g_wv16 : g_wo16;
        float4 v = ((const float4*)w)[i];
        ((half2*)o)[2 * i]     = __floats2half2_rn(v.x, v.y);
        ((half2*)o)[2 * i + 1] = __floats2half2_rn(v.z, v.w);
    }
}

// ---------------------------------------------------------------------------
// Merged QKV GEMM, occupancy-2, single sync/iter.
// ---------------------------------------------------------------------------
#define TCSTAGE 32768u
#define TC_SMEM_BYTES (3u * TCSTAGE)

struct QKVPtrs {
    const __nv_bfloat16* bhi[2];
    const __nv_bfloat16* blo[2];
    __nv_bfloat16* dhi[2];
    __nv_bfloat16* dlo[2];
    const __half* a16;
    const __half* wv16;
    __half* v16;
};

__global__ void __launch_bounds__(256, 2)
sgemm_qkv(const __nv_bfloat16* __restrict__ Ahi, const __nv_bfloat16* __restrict__ Alo,
          QKVPtrs P)
{
    extern __shared__ char smem[];
    const uint32_t sbase = smem_u32(smem);

    const int z = blockIdx.z;
    const int tid  = threadIdx.x;
    const int lane = tid & 31;
    const int w    = tid >> 5;
    const int m0w  = (w >> 2) * 64;
    const int n0w  = (w & 3) * 32;

    const int m0 = blockIdx.y * 128;
    const int n0 = blockIdx.x * 128;
    const int h  = blockIdx.x;

    float acc[4][4][4];
#pragma unroll
    for (int i = 0; i < 4; i++)
#pragma unroll
        for (int j = 0; j < 4; j++)
#pragma unroll
            for (int r = 0; r < 4; r++) acc[i][j][r] = 0.0f;

    const uint32_t arow = (uint32_t)(m0w + (lane & 15));
    const uint32_t acol = (uint32_t)((lane >> 4) << 4);
    const uint32_t browx = (uint32_t)(n0w + (lane & 7) + ((lane >> 4) << 3));
    const uint32_t bcol  = (uint32_t)(((lane >> 3) & 1) << 4);

    if (z == 2) {
        // ---------------- V path: fp16 single-product, BK=64 ----------------
        const __half* __restrict__ A16 = P.a16;
        const __half* __restrict__ B16 = P.wv16;

        uint32_t swofs[4];
#pragma unroll
        for (int t = 0; t < 4; t++) {
            const int u = tid + (t << 8);
            swofs[t] = swz128((uint32_t)((u >> 3) * 128 + (u & 7) * 16));
        }

#define LOAD_CHUNK16(c, buf)                                                   \
    {                                                                          \
        const uint32_t bofs = sbase + (uint32_t)(buf) * TCSTAGE;               \
        const int k0 = (c) * 64;                                               \
        _Pragma("unroll")                                                      \
        for (int t = 0; t < 4; t++) {                                          \
            const int u = tid + (t << 8);                                      \
            const int r = u >> 3;                                              \
            const int c16 = u & 7;                                             \
            const size_t ga = (size_t)(m0 + r) * D_ + k0 + c16 * 8;            \
            const size_t gb = (size_t)(n0 + r) * D_ + k0 + c16 * 8;            \
            cp16(bofs + 0u + swofs[t], A16 + ga);                              \
            cp16(bofs + 16384u + swofs[t], B16 + gb);                          \
        }                                                                      \
        CP_COMMIT();                                                           \
    }

        LOAD_CHUNK16(0, 0);
        LOAD_CHUNK16(1, 1);

        int buf = 0;
        for (int c = 0; c < 32; c++) {
            if (c < 31) {
                asm volatile("cp.async.wait_group 1;" ::: "memory");
            } else {
                asm volatile("cp.async.wait_group 0;" ::: "memory");
            }
            __syncthreads();
            if (c + 2 < 32) {
                const int nb = (buf + 2 >= 3) ? buf - 1 : buf + 2;
                LOAD_CHUNK16(c + 2, nb);
            }

            const uint32_t bofs = sbase + (uint32_t)buf * TCSTAGE;
            const uint32_t Ab = bofs;
            const uint32_t Bb = bofs + 16384u;

#pragma unroll
            for (int kk = 0; kk < 4; kk++) {
                uint32_t ah[4][4], bh[4][2];
                const uint32_t kb = (uint32_t)(kk * 32);
#pragma unroll
                for (int mt = 0; mt < 4; mt++) {
                    const uint32_t ofs = swz128((arow + mt * 16u) * 128u + acol + kb);
                    ldsm_x4(Ab + ofs, ah[mt]);
                }
#pragma unroll
                for (int ntp = 0; ntp < 2; ntp++) {
                    const uint32_t ofs = swz128((browx + ntp * 16u) * 128u + bcol + kb);
                    uint32_t b4[4];
                    ldsm_x4(Bb + ofs, b4);
                    bh[2 * ntp][0] = b4[0];     bh[2 * ntp][1] = b4[1];
                    bh[2 * ntp + 1][0] = b4[2]; bh[2 * ntp + 1][1] = b4[3];
                }
#pragma unroll
                for (int mt = 0; mt < 4; mt++)
#pragma unroll
                    for (int nt = 0; nt < 4; nt++)
                        mma16816h(acc[mt][nt], ah[mt], bh[nt]);
            }
            buf = (buf + 1 >= 3) ? 0 : buf + 1;
        }

        __half* __restrict__ C16 = P.v16;
        const int lr = lane >> 2;
        const int lc = (lane & 3) * 2;
#pragma unroll
        for (int mt = 0; mt < 4; mt++)
#pragma unroll
            for (int rr = 0; rr < 2; rr++) {
                const int m = m0 + m0w + mt * 16 + rr * 8 + lr;
                const int e = rr * 2;
                const int bb = m >> 11, s = m & (S_ - 1);
                const size_t rowoff = ((size_t)(bb * H_) * S_ + s) * HD_;
#pragma unroll
                for (int nt = 0; nt < 4; nt++) {
                    const int n = n0 + n0w + nt * 8 + lc;
                    const int hh = n >> 7, hd = n & 127;
                    *(half2*)&C16[rowoff + (size_t)hh * S_ * HD_ + hd] =
                        __floats2half2_rn(acc[mt][nt][e], acc[mt][nt][e + 1]);
                }
            }
        return;
    }

    // ---------------- Q/K path: bf16 3-product, BK=32 (swz64) ----------------
    const __nv_bfloat16* __restrict__ Bhi = P.bhi[z];
    const __nv_bfloat16* __restrict__ Blo = P.blo[z];
    __nv_bfloat16* __restrict__ Dhi = P.dhi[z];
    __nv_bfloat16* __restrict__ Dlo = P.dlo[z];

    uint32_t swofs2[2];
#pragma unroll
    for (int t = 0; t < 2; t++) {
        const int u = tid + (t << 8);
        swofs2[t] = swz64((uint32_t)((u >> 2) * 64 + (u & 3) * 16));
    }

#define LOAD_CHUNKQ(c, buf)                                                    \
    {                                                                          \
        const uint32_t bofs = sbase + (uint32_t)(buf) * TCSTAGE;               \
        const int k0 = (c) * 32;                                               \
        _Pragma("unroll")                                                      \
        for (int t = 0; t < 2; t++) {                                          \
            const int u = tid + (t << 8);                                      \
            const int r = u >> 2;                                              \
            const int c16 = u & 3;                                             \
            const size_t ga = (size_t)(m0 + r) * D_ + k0 + c16 * 8;            \
            const size_t gb = (size_t)(n0 + r) * D_ + k0 + c16 * 8;            \
            cp16(bofs + 0u     + swofs2[t], Ahi + ga);                         \
            cp16(bofs + 8192u  + swofs2[t], Alo + ga);                         \
            cp16(bofs + 16384u + swofs2[t], Bhi + gb);                         \
            cp16(bofs + 24576u + swofs2[t], Blo + gb);                         \
        }                                                                      \
        CP_COMMIT();                                                           \
    }

    LOAD_CHUNKQ(0, 0);
    LOAD_CHUNKQ(1, 1);

    int buf = 0;
    for (int c = 0; c < 64; c++) {
        if (c < 63) {
            asm volatile("cp.async.wait_group 1;" ::: "memory");
        } else {
            asm volatile("cp.async.wait_group 0;" ::: "memory");
        }
        __syncthreads();
        if (c + 2 < 64) {
            const int nb = (buf + 2 >= 3) ? buf - 1 : buf + 2;
            LOAD_CHUNKQ(c + 2, nb);
        }

        const uint32_t bofs = sbase + (uint32_t)buf * TCSTAGE;
        const uint32_t Ab_hi = bofs;
        const uint32_t Ab_lo = bofs + 8192u;
        const uint32_t Bb_hi = bofs + 16384u;
        const uint32_t Bb_lo = bofs + 24576u;

#pragma unroll
        for (int kk = 0; kk < 2; kk++) {
            uint32_t ah[4][4], al[4][4], bh[4][2], bl[4][2];
            const uint32_t kb = (uint32_t)(kk * 32);
#pragma unroll
            for (int mt = 0; mt < 4; mt++) {
                const uint32_t ofs = swz64((arow + mt * 16u) * 64u + acol + kb);
                ldsm_x4(Ab_hi + ofs, ah[mt]);
                ldsm_x4(Ab_lo + ofs, al[mt]);
            }
#pragma unroll
            for (int ntp = 0; ntp < 2; ntp++) {
                const uint32_t ofs = swz64((browx + ntp * 16u) * 64u + bcol + kb);
                uint32_t b4h[4], b4l[4];
                ldsm_x4(Bb_hi + ofs, b4h);
                ldsm_x4(Bb_lo + ofs, b4l);
                bh[2 * ntp][0] = b4h[0];     bh[2 * ntp][1] = b4h[1];
                bh[2 * ntp + 1][0] = b4h[2]; bh[2 * ntp + 1][1] = b4h[3];
                bl[2 * ntp][0] = b4l[0];     bl[2 * ntp][1] = b4l[1];
                bl[2 * ntp + 1][0] = b4l[2]; bl[2 * ntp + 1][1] = b4l[3];
            }
#pragma unroll
            for (int mt = 0; mt < 4; mt++)
#pragma unroll
                for (int nt = 0; nt < 4; nt++) {
                    mma16816(acc[mt][nt], ah[mt], bh[nt]);
                    mma16816(acc[mt][nt], ah[mt], bl[nt]);
                    mma16816(acc[mt][nt], al[mt], bh[nt]);
                }
        }
        buf = (buf + 1 >= 3) ? 0 : buf + 1;
    }

    // epilogue: stage fp32 tile, rope, split, store bf16 hi/lo
    __syncthreads();   // all warps done reading stage buffers before Cs overlay
    float* Cs = (float*)smem;
    const int lr = lane >> 2;
    const int lc = (lane & 3) * 2;
#pragma unroll
    for (int mt = 0; mt < 4; mt++)
#pragma unroll
        for (int rr = 0; rr < 2; rr++) {
            const int rloc = m0w + mt * 16 + rr * 8 + lr;
            const int e = rr * 2;
#pragma unroll
            for (int nt = 0; nt < 4; nt++) {
                const int nloc = n0w + nt * 8 + lc;
                *(float2*)&Cs[rloc * 132 + nloc] =
                    make_float2(acc[mt][nt][e], acc[mt][nt][e + 1]);
            }
        }
    __syncthreads();

    const float scq = (z == 0) ? 0.08838834764831845f : 1.0f;
    for (int i = tid; i < 128 * 32; i += 256) {
        const int r  = i >> 5;
        const int c0 = (i & 31) * 2;
        const int m  = m0 + r;
        const int s  = m & (S_ - 1);
        const int bb = m >> 11;
        const float2 v1 = *(float2*)&Cs[r * 132 + c0];
        const float2 v2 = *(float2*)&Cs[r * 132 + c0 + 64];
        const int ti = (s << 6) + c0;
        const float c_0 = g_cos[ti],     s_0 = g_sin[ti];
        const float c_1 = g_cos[ti + 1], s_1 = g_sin[ti + 1];
        const float o1_0 = (v1.x * c_0 - v2.x * s_0) * scq;
        const float o1_1 = (v1.y * c_1 - v2.y * s_1) * scq;
        const float o2_0 = (v1.x * s_0 + v2.x * c_0) * scq;
        const float o2_1 = (v1.y * s_1 + v2.y * c_1) * scq;

        __nv_bfloat16 h0, l0, h1, l1, h2, l2, h3, l3;
        split1(o1_0, h0, l0); split1(o1_1, h1, l1);
        split1(o2_0, h2, l2); split1(o2_1, h3, l3);

        const size_t base = ((size_t)(bb * H_ + h) * S_ + s) * HD_;
        *(__nv_bfloat162*)&Dhi[base + c0]      = __nv_bfloat162(h0, h1);
        *(__nv_bfloat162*)&Dlo[base + c0]      = __nv_bfloat162(l0, l1);
        *(__nv_bfloat162*)&Dhi[base + c0 + 64] = __nv_bfloat162(h2, h3);
        *(__nv_bfloat162*)&Dlo[base + c0 + 64] = __nv_bfloat162(l2, l3);
    }
}

// ---------------------------------------------------------------------------
// Output projection: fp16 single-product GEMM, occupancy 2, single sync/iter.
// ---------------------------------------------------------------------------
#define TC16_SMEM_BYTES (3u * TCSTAGE)

__global__ void __launch_bounds__(256, 2)
sgemm_out_f16(const __half* __restrict__ A16, const __half* __restrict__ B16,
              float* __restrict__ C)
{
    extern __shared__ char smem[];
    const uint32_t sbase = smem_u32(smem);

    const int tid  = threadIdx.x;
    const int lane = tid & 31;
    const int w    = tid >> 5;
    const int m0w  = (w >> 2) * 64;
    const int n0w  = (w & 3) * 32;

    const int m0 = blockIdx.y * 128;
    const int n0 = blockIdx.x * 128;

    uint32_t swofs[4];
#pragma unroll
    for (int t = 0; t < 4; t++) {
        const int u = tid + (t << 8);
        swofs[t] = swz128((uint32_t)((u >> 3) * 128 + (u & 7) * 16));
    }

    float acc[4][4][4];
#pragma unroll
    for (int i = 0; i < 4; i++)
#pragma unroll
        for (int j = 0; j < 4; j++)
#pragma unroll
            for (int r = 0; r < 4; r++) acc[i][j][r] = 0.0f;

    const uint32_t arow = (uint32_t)(m0w + (lane & 15));
    const uint32_t acol = (uint32_t)((lane >> 4) << 4);
    const uint32_t browx = (uint32_t)(n0w + (lane & 7) + ((lane >> 4) << 3));
    const uint32_t bcol  = (uint32_t)(((lane >> 3) & 1) << 4);

#define LOAD_CHUNKO(c, buf)                                                    \
    {                                                                          \
        const uint32_t bofs = sbase + (uint32_t)(buf) * TCSTAGE;               \
        const int k0 = (c) * 64;                                               \
        _Pragma("unroll")                                                      \
        for (int t = 0; t < 4; t++) {                                          \
            const int u = tid + (t << 8);                                      \
            const int r = u >> 3;                                              \
            const int c16 = u & 7;                                             \
            const size_t ga = (size_t)(m0 + r) * D_ + k0 + c16 * 8;            \
            const size_t gb = (size_t)(n0 + r) * D_ + k0 + c16 * 8;            \
            cp16(bofs + 0u + swofs[t], A16 + ga);                              \
            cp16(bofs + 16384u + swofs[t], B16 + gb);                          \
        }                                                                      \
        CP_COMMIT();                                                           \
    }

    LOAD_CHUNKO(0, 0);
    LOAD_CHUNKO(1, 1);

    int buf = 0;
    for (int c = 0; c < 32; c++) {
        if (c < 31) {
            asm volatile("cp.async.wait_group 1;" ::: "memory");
        } else {
            asm volatile("cp.async.wait_group 0;" ::: "memory");
        }
        __syncthreads();
        if (c + 2 < 32) {
            const int nb = (buf + 2 >= 3) ? buf - 1 : buf + 2;
            LOAD_CHUNKO(c + 2, nb);
        }

        const uint32_t bofs = sbase + (uint32_t)buf * TCSTAGE;
        const uint32_t Ab = bofs;
        const uint32_t Bb = bofs + 16384u;

#pragma unroll
        for (int kk = 0; kk < 4; kk++) {
            uint32_t ah[4][4], bh[4][2];
            const uint32_t kb = (uint32_t)(kk * 32);
#pragma unroll
            for (int mt = 0; mt < 4; mt++) {
                const uint32_t ofs = swz128((arow + mt * 16u) * 128u + acol + kb);
                ldsm_x4(Ab + ofs, ah[mt]);
            }
#pragma unroll
            for (int ntp = 0; ntp < 2; ntp++) {
                const uint32_t ofs = swz128((browx + ntp * 16u) * 128u + bcol + kb);
                uint32_t b4[4];
                ldsm_x4(Bb + ofs, b4);
                bh[2 * ntp][0] = b4[0];     bh[2 * ntp][1] = b4[1];
                bh[2 * ntp + 1][0] = b4[2]; bh[2 * ntp + 1][1] = b4[3];
            }
#pragma unroll
            for (int mt = 0; mt < 4; mt++)
#pragma unroll
                for (int nt = 0; nt < 4; nt++)
                    mma16816h(acc[mt][nt], ah[mt], bh[nt]);
        }
        buf = (buf + 1 >= 3) ? 0 : buf + 1;
    }

    const int lr = lane >> 2;
    const int lc = (lane & 3) * 2;
#pragma unroll
    for (int mt = 0; mt < 4; mt++) {
#pragma unroll
        for (int rr = 0; rr < 2; rr++) {
            const int m = m0 + m0w + mt * 16 + rr * 8 + lr;
            const int e = rr * 2;
            const size_t dstbase = (size_t)m * D_;
#pragma unroll
            for (int nt = 0; nt < 4; nt++) {
                const int n = n0 + n0w + nt * 8 + lc;
                *(float2*)&C[dstbase + n] =
                    make_float2(acc[mt][nt][e], acc[mt][nt][e + 1]);
            }
        }
    }
}

// ---------------------------------------------------------------------------
// Flash attention: 3-stage KV pipeline, prefetch distance 2, 1 sync/iter.
// ---------------------------------------------------------------------------
#define KVSTAGE 49152u
#define FL_SMEM (65536 + 3 * KVSTAGE)

__global__ void __launch_bounds__(256, 1)
flash_tc(const __nv_bfloat16* __restrict__ Qhi, const __nv_bfloat16* __restrict__ Qlo,
         const __nv_bfloat16* __restrict__ Khi, const __nv_bfloat16* __restrict__ Klo,
         const __half* __restrict__ V16,
         __half* __restrict__ AO16)
{
    extern __shared__ char smem[];
    const uint32_t sb = smem_u32(smem);
    const uint32_t sQh = sb;
    const uint32_t sQl = sb + 32768u;

    const int tid  = threadIdx.x;
    const int lane = tid & 31;
    const int w    = tid >> 5;
    const int lr   = lane >> 2;
    const int lc2  = (lane & 3) * 2;

    const int qt = (int)gridDim.x - 1 - (int)blockIdx.x;
    const int h  = blockIdx.y;
    const int b  = blockIdx.z;
    const size_t bh = ((size_t)(b * H_ + h)) * S_ * HD_;

    const __nv_bfloat16* Qhg = Qhi + bh + (size_t)qt * 128 * HD_;
    const __nv_bfloat16* Qlg = Qlo + bh + (size_t)qt * 128 * HD_;

    for (int i = tid; i < 2048; i += 256) {
        const uint32_t r = (uint32_t)(i >> 4);
        const uint32_t cb = (uint32_t)((i & 15) << 4);
        const uint32_t so = swzf(r, cb);
        cp16(sQh + so, Qhg + (size_t)r * HD_ + (i & 15) * 8);
        cp16(sQl + so, Qlg + (size_t)r * HD_ + (i & 15) * 8);
    }
    CP_COMMIT();   // group: Q

#define LOAD_KV(jj, buf)                                                       \
    {                                                                          \
        const uint32_t kvb = sb + 65536u + (uint32_t)(buf) * KVSTAGE;          \
        const size_t rg0 = (size_t)(jj) * 64;                                  \
        for (int i = tid; i < 1024; i += 256) {                                \
            const uint32_t r = (uint32_t)(i >> 4);                             \
            const uint32_t cb = (uint32_t)((i & 15) << 4);                     \
            const uint32_t so = swzf(r, cb);                                   \
            const size_t g = bh + (rg0 + r) * HD_ + (i & 15) * 8;              \
            cp16(kvb + so, Khi + g);                                           \
            cp16(kvb + 16384u + so, Klo + g);                                  \
            cp16(kvb + 32768u + so, V16 + g);                                  \
        }                                                                      \
    }

    const int jmax = 2 * qt + 1;

    LOAD_KV(0, 0);
    CP_COMMIT();   // group: KV0
    LOAD_KV(1, 1); // jmax >= 1 always
    CP_COMMIT();   // group: KV1

    // ---- hoist Q fragments: wait until only KV0,KV1 pending (Q done) ----
    asm volatile("cp.async.wait_group 2;" ::: "memory");
    __syncthreads();
    uint32_t qfh[8][4], qfl[8][4];
#pragma unroll
    for (int kc = 0; kc < 8; kc++) {
        const uint32_t ao_ = swzf((uint32_t)(w * 16 + (lane & 15)),
                                  (uint32_t)(kc * 32 + ((lane >> 4) << 4)));
        ldsm_x4(sQh + ao_, qfh[kc]);
        ldsm_x4(sQl + ao_, qfl[kc]);
    }

    float o[16][4];
#pragma unroll
    for (int i = 0; i < 16; i++)
#pragma unroll
        for (int e = 0; e < 4; e++) o[i][e] = 0.0f;
    float m0 = -1e30f, m1 = -1e30f, l0 = 0.0f, l1 = 0.0f;

    const int rbase = qt * 128 + w * 16 + lr;

    const uint32_t krowx = (uint32_t)((lane & 7) + ((lane >> 4) << 3));
    const uint32_t kcolx = (uint32_t)(((lane >> 3) & 1) << 4);

    int stage = 0;
    for (int j = 0; j <= jmax; j++) {
        if (j < jmax) {
            asm volatile("cp.async.wait_group 1;" ::: "memory");
        } else {
            asm volatile("cp.async.wait_group 0;" ::: "memory");
        }
        __syncthreads();
        if (j + 2 <= jmax) {
            const int nb = (stage + 2 >= 3) ? stage - 1 : stage + 2;
            LOAD_KV(j + 2, nb);
            CP_COMMIT();
        }

        const bool active = !(j == jmax && w < 4);
        if (active) {
        const uint32_t kvb = sb + 65536u + (uint32_t)stage * KVSTAGE;
        const uint32_t sKh = kvb;
        const uint32_t sKl = kvb + 16384u;
        const uint32_t sV  = kvb + 32768u;

        float sacc[8][4];
#pragma unroll
        for (int nt = 0; nt < 8; nt++)
#pragma unroll
            for (int e = 0; e < 4; e++) sacc[nt][e] = 0.0f;

#pragma unroll
        for (int kc = 0; kc < 8; kc++) {
#pragma unroll
            for (int ntp = 0; ntp < 4; ntp++) {
                const uint32_t bo = swzf(krowx + ntp * 16u,
                                         (uint32_t)(kc * 32) + kcolx);
                uint32_t b4h[4], b4l[4];
                ldsm_x4(sKh + bo, b4h);
                ldsm_x4(sKl + bo, b4l);
                mma16816(sacc[2 * ntp],     qfh[kc], &b4h[0]);
                mma16816(sacc[2 * ntp],     qfh[kc], &b4l[0]);
                mma16816(sacc[2 * ntp],     qfl[kc], &b4h[0]);
                mma16816(sacc[2 * ntp + 1], qfh[kc], &b4h[2]);
                mma16816(sacc[2 * ntp + 1], qfh[kc], &b4l[2]);
                mma16816(sacc[2 * ntp + 1], qfl[kc], &b4h[2]);
            }
        }

        if (j >= 2 * qt) {
            const int cb0 = j * 64 + lc2;
#pragma unroll
            for (int nt = 0; nt < 8; nt++)
#pragma unroll
                for (int e = 0; e < 4; e++) {
                    const int col = cb0 + nt * 8 + (e & 1);
                    const int row = rbase + 8 * (e >> 1);
                    if (col > row) sacc[nt][e] = -1e30f;
                }
        }

        float mx0 = -1e30f, mx1 = -1e30f;
#pragma unroll
        for (int nt = 0; nt < 8; nt++) {
            mx0 = fmaxf(mx0, fmaxf(sacc[nt][0], sacc[nt][1]));
            mx1 = fmaxf(mx1, fmaxf(sacc[nt][2], sacc[nt][3]));
        }
        mx0 = fmaxf(mx0, __shfl_xor_sync(0xffffffffu, mx0, 1));
        mx0 = fmaxf(mx0, __shfl_xor_sync(0xffffffffu, mx0, 2));
        mx1 = fmaxf(mx1, __shfl_xor_sync(0xffffffffu, mx1, 1));
        mx1 = fmaxf(mx1, __shfl_xor_sync(0xffffffffu, mx1, 2));

        const float mn0 = fmaxf(m0, mx0);
        const float mn1 = fmaxf(m1, mx1);
        const float al0 = __expf(m0 - mn0);
        const float al1 = __expf(m1 - mn1);
        m0 = mn0; m1 = mn1;

        float s0 = 0.0f, s1 = 0.0f;
#pragma unroll
        for (int nt = 0; nt < 8; nt++) {
            sacc[nt][0] = __expf(sacc[nt][0] - mn0); s0 += sacc[nt][0];
            sacc[nt][1] = __expf(sacc[nt][1] - mn0); s0 += sacc[nt][1];
            sacc[nt][2] = __expf(sacc[nt][2] - mn1); s1 += sacc[nt][2];
            sacc[nt][3] = __expf(sacc[nt][3] - mn1); s1 += sacc[nt][3];
        }
        s0 += __shfl_xor_sync(0xffffffffu, s0, 1);
        s0 += __shfl_xor_sync(0xffffffffu, s0, 2);
        s1 += __shfl_xor_sync(0xffffffffu, s1, 1);
        s1 += __shfl_xor_sync(0xffffffffu, s1, 2);
        l0 = l0 * al0 + s0;
        l1 = l1 * al1 + s1;

#pragma unroll
        for (int dt = 0; dt < 16; dt++) {
            o[dt][0] *= al0; o[dt][1] *= al0;
            o[dt][2] *= al1; o[dt][3] *= al1;
        }

#pragma unroll
        for (int t = 0; t < 4; t++) {
            uint32_t ph[4];
#pragma unroll
            for (int q2 = 0; q2 < 2; q2++)
#pragma unroll
                for (int rr = 0; rr < 2; rr++)
                    ph[q2 * 2 + rr] = packh2(sacc[2 * t + q2][2 * rr],
                                             sacc[2 * t + q2][2 * rr + 1]);
#pragma unroll
            for (int dtp = 0; dtp < 8; dtp++) {
                const uint32_t bo = swzf((uint32_t)(t * 16 + (lane & 15)),
                                         (uint32_t)((2 * dtp + (lane >> 4)) * 16));
                uint32_t b4[4];
                ldsm_x4t(sV + bo, b4);
                mma16816h(o[2 * dtp],     ph, &b4[0]);
                mma16816h(o[2 * dtp + 1], ph, &b4[2]);
            }
        }
        } // active
        stage = (stage + 1 >= 3) ? 0 : stage + 1;
    }

    const float inv0 = 1.0f / l0;
    const float inv1 = 1.0f / l1;
    const int srow0 = qt * 128 + w * 16 + lr;
    const size_t d0 = ((size_t)(b * S_ + srow0)) * D_ + h * HD_;
    const size_t d1 = ((size_t)(b * S_ + srow0 + 8)) * D_ + h * HD_;
#pragma unroll
    for (int dt = 0; dt < 16; dt++) {
        *(half2*)&AO16[d0 + dt * 8 + lc2] =
            __floats2half2_rn(o[dt][0] * inv0, o[dt][1] * inv0);
        *(half2*)&AO16[d1 + dt * 8 + lc2] =
            __floats2half2_rn(o[dt][2] * inv1, o[dt][3] * inv1);
    }
}

// ---------------------------------------------------------------------------
extern "C" void kernel_launch(void* const* d_in, const int* in_sizes, int n_in,
                              void* d_out, int out_size)
{
    (void)in_sizes; (void)n_in; (void)out_size;
    const float* x  = (const float*)d_in[0];
    const float* Wq = (const float*)d_in[2];
    const float* Wk = (const float*)d_in[3];
    const float* Wv = (const float*)d_in[4];
    const float* Wo = (const float*)d_in[5];
    float* out = (float*)d_out;

    __nv_bfloat16 *xhi, *xlo;
    __nv_bfloat16 *wqhi, *wqlo, *wkhi, *wklo;
    __nv_bfloat16 *qh, *ql, *kh, *kl;
    __half *x16, *wv16, *wo16, *ao16, *v16;
    cudaGetSymbolAddress((void**)&xhi, g_xhi);
    cudaGetSymbolAddress((void**)&xlo, g_xlo);
    cudaGetSymbolAddress((void**)&x16, g_x16);
    cudaGetSymbolAddress((void**)&wqhi, g_wqhi);
    cudaGetSymbolAddress((void**)&wqlo, g_wqlo);
    cudaGetSymbolAddress((void**)&wkhi, g_wkhi);
    cudaGetSymbolAddress((void**)&wklo, g_wklo);
    cudaGetSymbolAddress((void**)&wv16, g_wv16);
    cudaGetSymbolAddress((void**)&wo16, g_wo16);
    cudaGetSymbolAddress((void**)&ao16, g_ao16);
    cudaGetSymbolAddress((void**)&v16, g_v16);
    cudaGetSymbolAddress((void**)&qh, g_qh);
    cudaGetSymbolAddress((void**)&ql, g_ql);
    cudaGetSymbolAddress((void**)&kh, g_kh);
    cudaGetSymbolAddress((void**)&kl, g_kl);

    cudaFuncSetAttribute(sgemm_qkv,
                         cudaFuncAttributeMaxDynamicSharedMemorySize, TC_SMEM_BYTES);
    cudaFuncSetAttribute(sgemm_out_f16,
                         cudaFuncAttributeMaxDynamicSharedMemorySize, TC16_SMEM_BYTES);
    cudaFuncSetAttribute(flash_tc,
                         cudaFuncAttributeMaxDynamicSharedMemorySize, FL_SMEM);

    // 1) all prep in one launch
    prep_all<<<PREP_BLOCKS, 256>>>(x, Wq, Wk, Wv, Wo);

    // 2) merged QKV projections (occupancy 2)
    QKVPtrs P;
    P.bhi[0] = wqhi; P.blo[0] = wqlo; P.dhi[0] = qh; P.dlo[0] = ql;
    P.bhi[1] = wkhi; P.blo[1] = wklo; P.dhi[1] = kh; P.dlo[1] = kl;
    P.a16 = x16; P.wv16 = wv16; P.v16 = v16;
    dim3 qkvgrid(D_ / 128, (B_ * S_) / 128, 3);
    sgemm_qkv<<<qkvgrid, 256, TC_SMEM_BYTES>>>(xhi, xlo, P);

    // 3) attention (3-stage pipeline)
    flash_tc<<<dim3(S_ / 128, H_, B_), 256, FL_SMEM>>>(qh, ql, kh, kl, v16, ao16);

    // 4) output projection (occupancy 2)
    dim3 ggrid(D_ / 128, (B_ * S_) / 128);
    sgemm_out_f16<<<ggrid, 256, TC16_SMEM_BYTES>>>(ao16, wo16, out);
}